// round 13
// baseline (speedup 1.0000x reference)
#include <cuda_runtime.h>

// ---------------------------------------------------------------------------
// LeNet-5 forward, B=8192, fp32.
//   prep : pooled-effective 6x6 filters (conv5x5+avgpool fused), slopes folded
//   K12  : C1+S2+act then C3+S4+act, 8 images/block, 384 threads.
//          Phase 2: och-grouped warps (4 och/warp) iterate only connected
//          input channels (c_nic sorted) -> 51/72 of dense ic work.
//   K3   : C5 (+bias) -> C[8192][480]; 28 img/block, grid 293 = ONE wave
//   K4   : F6+act+RBF -> out[32768][10]; 112 rows/block, ONE wave (R10 ver)
// ---------------------------------------------------------------------------

#define ACT_SCALE 1.7159f
#define ACT_SLOPE (2.0f / 3.0f)

typedef unsigned long long u64;

__device__ __forceinline__ void fma2(u64& d, u64 a, u64 b) {
    asm("fma.rn.f32x2 %0, %1, %2, %0;" : "+l"(d) : "l"(a), "l"(b));
}
__device__ __forceinline__ float hsum2(u64 v) {
    float lo, hi; asm("mov.b64 {%0, %1}, %2;" : "=f"(lo), "=f"(hi) : "l"(v));
    return lo + hi;
}
__device__ __forceinline__ float fast_tanh(float x) {
    float e = __expf(2.0f * x);
    return 1.0f - __fdividef(2.0f, e + 1.0f);
}

// bit i of c_cmask[o] set iff input channel i feeds output channel o (MAP_INFO)
static __constant__ unsigned c_cmask[16] = {
    7u, 14u, 28u, 56u, 49u, 35u, 15u, 30u,
    60u, 57u, 51u, 39u, 27u, 54u, 45u, 63u
};
// connected input-channel lists per output channel (derived from MAP_INFO)
static __constant__ int c_nic[16]   = {3,3,3,3,3,3,4,4,4,4,4,4,4,4,4,6};
static __constant__ int c_clist[16][6] = {
    {0,1,2,0,0,0}, {1,2,3,0,0,0}, {2,3,4,0,0,0}, {3,4,5,0,0,0},
    {0,4,5,0,0,0}, {0,1,5,0,0,0}, {0,1,2,3,0,0}, {1,2,3,4,0,0},
    {2,3,4,5,0,0}, {0,3,4,5,0,0}, {0,1,4,5,0,0}, {0,1,2,5,0,0},
    {0,1,3,4,0,0}, {1,2,4,5,0,0}, {0,2,3,5,0,0}, {0,1,2,3,4,5}
};

// Scratch (module-static device memory; no runtime allocation)
__device__ float g_B[8192 * 16 * 6 * 6];
__device__ float g_C[8192 * 480];
__device__ __align__(16) float g_w6c1[6 * 36];
__device__ float g_bf1[6];
__device__ __align__(16) float g_w6c3[16 * 6 * 36];
__device__ float g_bf3[16];

// ---------------------------------------------------------------------------
__global__ void k_prep(const float* __restrict__ c1_w, const float* __restrict__ c1_b,
                       const float* __restrict__ s2_w, const float* __restrict__ s2_b,
                       const float* __restrict__ c3_w, const float* __restrict__ c3_b,
                       const float* __restrict__ s4_w, const float* __restrict__ s4_b) {
    int t = threadIdx.x;
    for (int idx = t; idx < 216; idx += 256) {
        int c = idx / 36, a = (idx % 36) / 6, b = idx % 6;
        float s = 0.f;
        #pragma unroll
        for (int di = 0; di < 2; di++)
            #pragma unroll
            for (int dj = 0; dj < 2; dj++) {
                int u = a - di, v = b - dj;
                if (u >= 0 && u < 5 && v >= 0 && v < 5)
                    s += c1_w[(c * 5 + u) * 5 + v];
            }
        g_w6c1[idx] = 0.25f * ACT_SLOPE * s2_w[c] * s;
    }
    if (t < 6) g_bf1[t] = ACT_SLOPE * (s2_w[t] * c1_b[t] + s2_b[t]);
    for (int idx = t; idx < 3456; idx += 256) {
        int o = idx / 216;
        int i = (idx % 216) / 36;
        int ab = idx % 36;
        int a = ab / 6, b = ab % 6;
        float s = 0.f;
        #pragma unroll
        for (int di = 0; di < 2; di++)
            #pragma unroll
            for (int dj = 0; dj < 2; dj++) {
                int u = a - di, v = b - dj;
                if (u >= 0 && u < 5 && v >= 0 && v < 5)
                    s += c3_w[((o * 6 + i) * 5 + u) * 5 + v];
            }
        float m = ((c_cmask[o] >> i) & 1u) ? 1.f : 0.f;
        g_w6c3[idx] = m * 0.25f * ACT_SLOPE * s4_w[o] * s;
    }
    if (t < 16) g_bf3[t] = ACT_SLOPE * (s4_w[t] * c3_b[t] + s4_b[t]);
}

// ---------------------------------------------------------------------------
// K12: fused C1+S2+act and C3+S4+act.  8 images/block, 384 threads.
// sA image stride 1540 (mod 32 = 4): phase-2 img-lanes hit distinct banks.
// ---------------------------------------------------------------------------
#define K12_IMG 8
#define K12_THREADS 384
#define SA_STRIDE 1540
#define K12_SMEM ((K12_IMG * 1296 + K12_IMG * SA_STRIDE + 216 + 3456 + 8 + 16) * 4)

__global__ void __launch_bounds__(K12_THREADS) k12(const float* __restrict__ x) {
    extern __shared__ __align__(16) float sm12[];
    float* sinb = sm12;                          // [8][1296]
    float* sAb  = sinb + K12_IMG * 1296;         // [8][1540] (1536 used)
    float* sw1  = sAb + K12_IMG * SA_STRIDE;     // [216]
    float* sw3  = sw1 + 216;                     // [3456]
    float* sb1  = sw3 + 3456;                    // [8] (6 used)
    float* sb3  = sb1 + 8;                       // [16]
    int t = threadIdx.x;
    long img0 = (long)blockIdx.x * K12_IMG;

    for (int idx = t; idx < 216; idx += K12_THREADS) sw1[idx] = g_w6c1[idx];
    for (int idx = t; idx < 3456; idx += K12_THREADS) sw3[idx] = g_w6c3[idx];
    if (t < 6) sb1[t] = g_bf1[t];
    if (t < 16) sb3[t] = g_bf3[t];
    for (int idx = t; idx < K12_IMG * 1296; idx += K12_THREADS) {
        int m = idx / 1296, p = idx % 1296;
        int r = p / 36, c = p % 36;
        int sr = min(max(r - 2, 0), 31);
        int sc = min(max(c - 2, 0), 31);
        sinb[m * 1296 + p] = x[(img0 + m) * 1024 + sr * 32 + sc];
    }
    __syncthreads();

    // ---- Phase 1: C1+S2+act (R10 mapping) ----
    {
        int pr = t >> 3;          // 0..47 = img*6 + ch
        int q = t & 7;
        int img = pr / 6, ch = pr % 6;
        float4 w4[9];
        float* w = (float*)w4;
        #pragma unroll
        for (int v = 0; v < 9; v++)
            w4[v] = ((const float4*)(sw1 + ch * 36))[v];
        float bias = sb1[ch];
        #pragma unroll
        for (int tl = 0; tl < 8; tl++) {
            const float* bp = sinb + img * 1296 + (4 * tl) * 36 + 4 * q;
            float a00 = 0.f, a01 = 0.f, a10 = 0.f, a11 = 0.f;
            #pragma unroll
            for (int row = 0; row < 8; row++) {
                float2 rv2[4];
                float* rv = (float*)rv2;
                #pragma unroll
                for (int h = 0; h < 4; h++)
                    rv2[h] = *(const float2*)(bp + row * 36 + 2 * h);
                if (row < 6) {
                    #pragma unroll
                    for (int s = 0; s < 6; s++) {
                        float wv = w[row * 6 + s];
                        a00 = fmaf(wv, rv[s], a00);
                        a01 = fmaf(wv, rv[2 + s], a01);
                    }
                }
                if (row >= 2) {
                    #pragma unroll
                    for (int s = 0; s < 6; s++) {
                        float wv = w[(row - 2) * 6 + s];
                        a10 = fmaf(wv, rv[s], a10);
                        a11 = fmaf(wv, rv[2 + s], a11);
                    }
                }
            }
            float* op = sAb + img * SA_STRIDE + ch * 256 + (2 * tl) * 16 + 2 * q;
            op[0]  = ACT_SCALE * fast_tanh(a00 + bias);
            op[1]  = ACT_SCALE * fast_tanh(a01 + bias);
            op[16] = ACT_SCALE * fast_tanh(a10 + bias);
            op[17] = ACT_SCALE * fast_tanh(a11 + bias);
        }
    }
    __syncthreads();

    // ---- Phase 2: C3+S4+act, sparse connectivity ----
    // t = os*96 + iq*4 + oc ; och = os*4+oc (4 och per warp, nic-sorted),
    // img = iq%8, q = iq/8 ; tiles (ti,tj) = (u,q), u = 0..2.
    {
        int os = t / 96;
        int rem = t % 96;
        int iq = rem >> 2;
        int oc = rem & 3;
        int och = os * 4 + oc;
        int img = iq & 7;
        int q = iq >> 3;
        float bias = sb3[och];
        float acc[3][4];
        #pragma unroll
        for (int u = 0; u < 3; u++)
            #pragma unroll
            for (int z = 0; z < 4; z++) acc[u][z] = 0.f;

        int nic = c_nic[och];
        for (int j = 0; j < nic; j++) {
            int ic = c_clist[och][j];
            float4 w4[9];
            float* w = (float*)w4;
            #pragma unroll
            for (int z = 0; z < 9; z++)
                w4[z] = ((const float4*)(sw3 + och * 216 + ic * 36))[z];
            #pragma unroll
            for (int u = 0; u < 3; u++) {
                const float* bp = sAb + img * SA_STRIDE + ic * 256
                                + (4 * u) * 16 + 4 * q;
                #pragma unroll
                for (int row = 0; row < 8; row++) {
                    float2 rv2[4];
                    float* rv = (float*)rv2;
                    #pragma unroll
                    for (int h = 0; h < 4; h++)
                        rv2[h] = *(const float2*)(bp + row * 16 + 2 * h);
                    if (row < 6) {
                        #pragma unroll
                        for (int s = 0; s < 6; s++) {
                            float wv = w[row * 6 + s];
                            acc[u][0] = fmaf(wv, rv[s], acc[u][0]);
                            acc[u][1] = fmaf(wv, rv[2 + s], acc[u][1]);
                        }
                    }
                    if (row >= 2) {
                        #pragma unroll
                        for (int s = 0; s < 6; s++) {
                            float wv = w[(row - 2) * 6 + s];
                            acc[u][2] = fmaf(wv, rv[s], acc[u][2]);
                            acc[u][3] = fmaf(wv, rv[2 + s], acc[u][3]);
                        }
                    }
                }
            }
        }
        float* ob = g_B + (img0 + img) * 576 + och * 36;
        #pragma unroll
        for (int u = 0; u < 3; u++) {
            int r0 = 2 * u, c0 = 2 * q;
            ob[r0 * 6 + c0]           = ACT_SCALE * fast_tanh(acc[u][0] + bias);
            ob[r0 * 6 + c0 + 1]       = ACT_SCALE * fast_tanh(acc[u][1] + bias);
            ob[(r0 + 1) * 6 + c0]     = ACT_SCALE * fast_tanh(acc[u][2] + bias);
            ob[(r0 + 1) * 6 + c0 + 1] = ACT_SCALE * fast_tanh(acc[u][3] + bias);
        }
    }
}

// ---------------------------------------------------------------------------
// K3: C5 16->120 conv5x5 on 6x6 -> [2,2] positions (+bias).
// 28 images/block, 224 threads, 24-channel weight chunks [400][25] (5 exact
// chunks).  grid = 293 <= 296 concurrent CTAs -> single wave.
// ---------------------------------------------------------------------------
#define K3_IMG 28
#define K3_CHK 24
#define K3_THREADS 224
#define K3_INSTRIDE 584
#define K3_WSTRIDE  25
#define K3_SMEM ((K3_IMG * K3_INSTRIDE + 400 * K3_WSTRIDE) * 4)
#define K3_GRID ((8192 + K3_IMG - 1) / K3_IMG)

__global__ void __launch_bounds__(K3_THREADS) k3(const float* __restrict__ c5_w,
                                                 const float* __restrict__ c5_b) {
    extern __shared__ __align__(16) float sm3[];
    float* sin = sm3;                         // [28][584]
    float* swt = sm3 + K3_IMG * K3_INSTRIDE;  // [400][25] (k-major, ch minor)
    int t = threadIdx.x;
    long imgbase = (long)blockIdx.x * K3_IMG;
    for (int idx = t; idx < K3_IMG * 576; idx += K3_THREADS) {
        int im = idx / 576, off = idx % 576;
        long gi = imgbase + im;
        sin[im * K3_INSTRIDE + off] = (gi < 8192) ? g_B[gi * 576 + off] : 0.f;
    }
    int cg = t & 7;   // channel group (3 channels each, 8 groups = 24 ch)
    int pg = t >> 3;  // local image index 0..27
    const float* ip = sin + pg * K3_INSTRIDE;
    long gimg = imgbase + pg;
    float* outp = g_C + gimg * 480;

    for (int chunk = 0; chunk < 120; chunk += K3_CHK) {
        __syncthreads();
        for (int idx = t; idx < K3_CHK * 400; idx += K3_THREADS) {
            int ch = idx / 400, k = idx % 400;
            swt[k * K3_WSTRIDE + ch] = c5_w[(long)(chunk + ch) * 400 + k];
        }
        __syncthreads();

        float acc[4][3];
        #pragma unroll
        for (int p = 0; p < 4; p++)
            #pragma unroll
            for (int c = 0; c < 3; c++) acc[p][c] = 0.f;

        for (int ic = 0; ic < 16; ic++) {
            float4 pv4[9];
            float* pv = (float*)pv4;
            #pragma unroll
            for (int v = 0; v < 9; v++)
                pv4[v] = ((const float4*)(ip + ic * 36))[v];
            #pragma unroll
            for (int r = 0; r < 5; r++) {
                #pragma unroll
                for (int s = 0; s < 5; s++) {
                    const float* wk = swt + (ic * 25 + r * 5 + s) * K3_WSTRIDE + cg * 3;
                    float w0 = wk[0], w1 = wk[1], w2 = wk[2];
                    #pragma unroll
                    for (int pi = 0; pi < 2; pi++)
                        #pragma unroll
                        for (int pj = 0; pj < 2; pj++) {
                            float v = pv[(pi + r) * 6 + pj + s];
                            int p = pi * 2 + pj;
                            acc[p][0] = fmaf(v, w0, acc[p][0]);
                            acc[p][1] = fmaf(v, w1, acc[p][1]);
                            acc[p][2] = fmaf(v, w2, acc[p][2]);
                        }
                }
            }
        }
        if (gimg < 8192) {
            #pragma unroll
            for (int cc = 0; cc < 3; cc++) {
                int ch = chunk + cg * 3 + cc;
                float b = c5_b[ch];
                float4 o;
                o.x = acc[0][cc] + b;
                o.y = acc[1][cc] + b;
                o.z = acc[2][cc] + b;
                o.w = acc[3][cc] + b;
                *(float4*)(outp + ch * 4) = o;
            }
        }
    }
}

// ---------------------------------------------------------------------------
// K4: F6 (120->84) + act + RBF.  112 rows/block, 448 threads, one wave.
// Weights n-major [84][122]; FFMA2 over k (u64 loads — R10 version, 2 CTAs).
// ---------------------------------------------------------------------------
#define K4_ROWS 112
#define K4_THREADS 448
#define K4_GRID ((32768 + K4_ROWS - 1) / K4_ROWS)
#define K4_SMEM ((K4_ROWS * 122 + 84 * 122 + 840 + 84) * 4)

__global__ void __launch_bounds__(K4_THREADS) k4(const float* __restrict__ f6_w,
                                                 const float* __restrict__ f6_b,
                                                 const float* __restrict__ rbf_w,
                                                 float* __restrict__ out) {
    extern __shared__ __align__(16) float sm4[];
    float* srow = sm4;                   // [112][122]; later overlaid by sh [112][85]
    float* swt  = srow + K4_ROWS * 122;  // [84][122]  (n-major, pre-scaled)
    float* srbf = swt + 84 * 122;        // [84][10]
    float* sb6  = srbf + 840;            // [84]
    float* sh   = srow;                  // overlay
    int t = threadIdx.x, blk = blockIdx.x;
    long row0 = (long)blk * K4_ROWS;
    int nrows = (int)min((long)K4_ROWS, 32768l - row0);

    for (int idx = t; idx < K4_ROWS * 120; idx += K4_THREADS) {
        int r = idx / 120, k = idx % 120;
        srow[r * 122 + k] = (r < nrows) ? g_C[(row0 + r) * 120 + k] : 0.f;
    }
    for (int idx = t; idx < 84 * 120; idx += K4_THREADS) {
        int n = idx / 120, k = idx % 120;
        swt[n * 122 + k] = ACT_SLOPE * f6_w[idx];
    }
    for (int idx = t; idx < 840; idx += K4_THREADS) srbf[idx] = rbf_w[idx];
    if (t < 84) sb6[t] = ACT_SLOPE * f6_b[t];
    __syncthreads();

    int rg = t >> 4;    // 28 row-groups of 4 rows
    int cl = t & 15;    // column lane
    u64 acc[4][6];
    #pragma unroll
    for (int i = 0; i < 4; i++)
        #pragma unroll
        for (int q = 0; q < 6; q++) acc[i][q] = 0;

    const float* r0 = srow + (rg * 4 + 0) * 122;
    const float* r1 = srow + (rg * 4 + 1) * 122;
    const float* r2 = srow + (rg * 4 + 2) * 122;
    const float* r3 = srow + (rg * 4 + 3) * 122;
    for (int k = 0; k < 120; k += 2) {
        u64 v0 = *(const u64*)(r0 + k);
        u64 v1 = *(const u64*)(r1 + k);
        u64 v2 = *(const u64*)(r2 + k);
        u64 v3 = *(const u64*)(r3 + k);
        #pragma unroll
        for (int q = 0; q < 6; q++) {
            int n = cl + 16 * q;
            if (n < 84) {
                u64 w = *(const u64*)(swt + n * 122 + k);
                fma2(acc[0][q], v0, w);
                fma2(acc[1][q], v1, w);
                fma2(acc[2][q], v2, w);
                fma2(acc[3][q], v3, w);
            }
        }
    }
    float hv[4][6];
    #pragma unroll
    for (int q = 0; q < 6; q++) {
        int n = cl + 16 * q;
        if (n < 84) {
            float bias = sb6[n];
            #pragma unroll
            for (int i = 0; i < 4; i++)
                hv[i][q] = ACT_SCALE * fast_tanh(hsum2(acc[i][q]) + bias);
        }
    }
    __syncthreads();   // all reads of srow done before sh overlay writes
    #pragma unroll
    for (int q = 0; q < 6; q++) {
        int n = cl + 16 * q;
        if (n < 84) {
            #pragma unroll
            for (int i = 0; i < 4; i++)
                sh[(rg * 4 + i) * 85 + n] = hv[i][q];
        }
    }
    __syncthreads();

    for (int idx = t; idx < K4_ROWS * 10; idx += K4_THREADS) {
        int r = idx / 10, o = idx % 10;
        if (r < nrows) {
            const float* hr = sh + r * 85;
            float s = 0.f;
            #pragma unroll 4
            for (int n = 0; n < 84; n++) {
                float d = hr[n] - srbf[n * 10 + o];
                s = fmaf(d, d, s);
            }
            out[(row0 + r) * 10 + o] = s;
        }
    }
}

// ---------------------------------------------------------------------------
extern "C" void kernel_launch(void* const* d_in, const int* in_sizes, int n_in,
                              void* d_out, int out_size) {
    const float* x     = (const float*)d_in[0];
    const float* c1_w  = (const float*)d_in[1];
    const float* c1_b  = (const float*)d_in[2];
    const float* s2_w  = (const float*)d_in[3];
    const float* s2_b  = (const float*)d_in[4];
    const float* c3_w  = (const float*)d_in[5];
    const float* c3_b  = (const float*)d_in[6];
    const float* s4_w  = (const float*)d_in[7];
    const float* s4_b  = (const float*)d_in[8];
    const float* c5_w  = (const float*)d_in[9];
    const float* c5_b  = (const float*)d_in[10];
    const float* f6_w  = (const float*)d_in[11];
    const float* f6_b  = (const float*)d_in[12];
    const float* rbf_w = (const float*)d_in[13];

    cudaFuncSetAttribute(k12, cudaFuncAttributeMaxDynamicSharedMemorySize, K12_SMEM);
    cudaFuncSetAttribute(k3, cudaFuncAttributeMaxDynamicSharedMemorySize, K3_SMEM);
    cudaFuncSetAttribute(k4, cudaFuncAttributeMaxDynamicSharedMemorySize, K4_SMEM);

    k_prep<<<1, 256>>>(c1_w, c1_b, s2_w, s2_b, c3_w, c3_b, s4_w, s4_b);
    k12<<<8192 / K12_IMG, K12_THREADS, K12_SMEM>>>(x);
    k3<<<K3_GRID, K3_THREADS, K3_SMEM>>>(c5_w, c5_b);
    k4<<<K4_GRID, K4_THREADS, K4_SMEM>>>(f6_w, f6_b, rbf_w, (float*)d_out);
}

// round 14
// speedup vs baseline: 1.0680x; 1.0680x over previous
#include <cuda_runtime.h>

// ---------------------------------------------------------------------------
// LeNet-5 forward, B=8192, fp32.
//   prep : pooled-effective 6x6 filters (conv5x5+avgpool fused), slopes folded
//   K12  : C1+S2+act then C3+S4+act, 8 images/block, 384 threads, DENSE
//          phase 2 (R10 mapping); FFMA2 math via zero-cost u64 aliasing of
//          the float4/float2 operand arrays.
//   K3   : C5 (+bias) -> C[8192][480]; 28 img/block, grid 293 = ONE wave
//   K4   : F6+act+RBF -> out[32768][10]; 112 rows/block, ONE wave, FFMA2
// ---------------------------------------------------------------------------

#define ACT_SCALE 1.7159f
#define ACT_SLOPE (2.0f / 3.0f)

typedef unsigned long long u64;

__device__ __forceinline__ void fma2(u64& d, u64 a, u64 b) {
    asm("fma.rn.f32x2 %0, %1, %2, %0;" : "+l"(d) : "l"(a), "l"(b));
}
__device__ __forceinline__ float hsum2(u64 v) {
    float lo, hi; asm("mov.b64 {%0, %1}, %2;" : "=f"(lo), "=f"(hi) : "l"(v));
    return lo + hi;
}
__device__ __forceinline__ float fast_tanh(float x) {
    float e = __expf(2.0f * x);
    return 1.0f - __fdividef(2.0f, e + 1.0f);
}

// bit i of c_cmask[o] set iff input channel i feeds output channel o (MAP_INFO)
static __constant__ unsigned c_cmask[16] = {
    7u, 14u, 28u, 56u, 49u, 35u, 15u, 30u,
    60u, 57u, 51u, 39u, 27u, 54u, 45u, 63u
};

// Scratch (module-static device memory; no runtime allocation)
__device__ float g_B[8192 * 16 * 6 * 6];
__device__ float g_C[8192 * 480];
__device__ __align__(16) float g_w6c1[6 * 36];
__device__ float g_bf1[6];
__device__ __align__(16) float g_w6c3[16 * 6 * 36];
__device__ float g_bf3[16];

// ---------------------------------------------------------------------------
__global__ void k_prep(const float* __restrict__ c1_w, const float* __restrict__ c1_b,
                       const float* __restrict__ s2_w, const float* __restrict__ s2_b,
                       const float* __restrict__ c3_w, const float* __restrict__ c3_b,
                       const float* __restrict__ s4_w, const float* __restrict__ s4_b) {
    int t = threadIdx.x;
    for (int idx = t; idx < 216; idx += 256) {
        int c = idx / 36, a = (idx % 36) / 6, b = idx % 6;
        float s = 0.f;
        #pragma unroll
        for (int di = 0; di < 2; di++)
            #pragma unroll
            for (int dj = 0; dj < 2; dj++) {
                int u = a - di, v = b - dj;
                if (u >= 0 && u < 5 && v >= 0 && v < 5)
                    s += c1_w[(c * 5 + u) * 5 + v];
            }
        g_w6c1[idx] = 0.25f * ACT_SLOPE * s2_w[c] * s;
    }
    if (t < 6) g_bf1[t] = ACT_SLOPE * (s2_w[t] * c1_b[t] + s2_b[t]);
    for (int idx = t; idx < 3456; idx += 256) {
        int o = idx / 216;
        int i = (idx % 216) / 36;
        int ab = idx % 36;
        int a = ab / 6, b = ab % 6;
        float s = 0.f;
        #pragma unroll
        for (int di = 0; di < 2; di++)
            #pragma unroll
            for (int dj = 0; dj < 2; dj++) {
                int u = a - di, v = b - dj;
                if (u >= 0 && u < 5 && v >= 0 && v < 5)
                    s += c3_w[((o * 6 + i) * 5 + u) * 5 + v];
            }
        float m = ((c_cmask[o] >> i) & 1u) ? 1.f : 0.f;
        g_w6c3[idx] = m * 0.25f * ACT_SLOPE * s4_w[o] * s;
    }
    if (t < 16) g_bf3[t] = ACT_SLOPE * (s4_w[t] * c3_b[t] + s4_b[t]);
}

// ---------------------------------------------------------------------------
// K12: fused C1+S2+act and C3+S4+act.  8 images/block, 384 threads.
// FFMA2 math: weight pairs (w[row*6+2j], w[row*6+2j+1]) and input pairs are
// contiguous 8B words inside the float4/float2 arrays -> alias as u64, no MOVs.
// a00/a10 use input pair j; a01/a11 use pair j+1 (offset +2 floats = +1 pair).
// ---------------------------------------------------------------------------
#define K12_IMG 8
#define K12_THREADS 384
#define K12_SMEM ((K12_IMG * 1296 + K12_IMG * 1536 + 216 + 3456 + 8 + 16) * 4)

__global__ void __launch_bounds__(K12_THREADS) k12(const float* __restrict__ x) {
    extern __shared__ __align__(16) float sm12[];
    float* sinb = sm12;                        // [8][1296]
    float* sAb  = sinb + K12_IMG * 1296;       // [8][1536]
    float* sw1  = sAb + K12_IMG * 1536;        // [216]
    float* sw3  = sw1 + 216;                   // [3456]
    float* sb1  = sw3 + 3456;                  // [8] (6 used)
    float* sb3  = sb1 + 8;                     // [16]
    int t = threadIdx.x;
    long img0 = (long)blockIdx.x * K12_IMG;

    for (int idx = t; idx < 216; idx += K12_THREADS) sw1[idx] = g_w6c1[idx];
    for (int idx = t; idx < 3456; idx += K12_THREADS) sw3[idx] = g_w6c3[idx];
    if (t < 6) sb1[t] = g_bf1[t];
    if (t < 16) sb3[t] = g_bf3[t];
    for (int idx = t; idx < K12_IMG * 1296; idx += K12_THREADS) {
        int m = idx / 1296, p = idx % 1296;
        int r = p / 36, c = p % 36;
        int sr = min(max(r - 2, 0), 31);
        int sc = min(max(c - 2, 0), 31);
        sinb[m * 1296 + p] = x[(img0 + m) * 1024 + sr * 32 + sc];
    }
    __syncthreads();

    // ---- Phase 1: C1+S2+act ----
    {
        int pr = t >> 3;          // 0..47 = img*6 + ch
        int q = t & 7;
        int img = pr / 6, ch = pr % 6;
        float4 w4[9];
        const u64* wp = (const u64*)w4;   // wp[row*3+j] = pair (w[row*6+2j], +1)
        #pragma unroll
        for (int v = 0; v < 9; v++)
            w4[v] = ((const float4*)(sw1 + ch * 36))[v];
        float bias = sb1[ch];
        #pragma unroll
        for (int tl = 0; tl < 8; tl++) {
            const float* bp = sinb + img * 1296 + (4 * tl) * 36 + 4 * q;
            u64 a00 = 0, a01 = 0, a10 = 0, a11 = 0;
            #pragma unroll
            for (int row = 0; row < 8; row++) {
                float2 rv2[4];
                const u64* rp = (const u64*)rv2;
                #pragma unroll
                for (int h = 0; h < 4; h++)
                    rv2[h] = *(const float2*)(bp + row * 36 + 2 * h);
                if (row < 6) {
                    #pragma unroll
                    for (int j = 0; j < 3; j++) {
                        fma2(a00, wp[row * 3 + j], rp[j]);
                        fma2(a01, wp[row * 3 + j], rp[j + 1]);
                    }
                }
                if (row >= 2) {
                    #pragma unroll
                    for (int j = 0; j < 3; j++) {
                        fma2(a10, wp[(row - 2) * 3 + j], rp[j]);
                        fma2(a11, wp[(row - 2) * 3 + j], rp[j + 1]);
                    }
                }
            }
            float* op = sAb + img * 1536 + ch * 256 + (2 * tl) * 16 + 2 * q;
            op[0]  = ACT_SCALE * fast_tanh(hsum2(a00) + bias);
            op[1]  = ACT_SCALE * fast_tanh(hsum2(a01) + bias);
            op[16] = ACT_SCALE * fast_tanh(hsum2(a10) + bias);
            op[17] = ACT_SCALE * fast_tanh(hsum2(a11) + bias);
        }
    }
    __syncthreads();

    // ---- Phase 2: C3+S4+act (dense; masked weights are zero) ----
    {
        int pr = t / 3;           // 0..127 = img*16 + och
        int q = t % 3;
        int img = pr >> 4, och = pr & 15;
        float bias = sb3[och];
        u64 acc[3][4];
        #pragma unroll
        for (int u = 0; u < 3; u++)
            #pragma unroll
            for (int z = 0; z < 4; z++) acc[u][z] = 0;
        int ti_[3], tj_[3];
        #pragma unroll
        for (int u = 0; u < 3; u++) {
            int tile = q + u * 3;       // 0..8
            ti_[u] = tile / 3;
            tj_[u] = tile % 3;
        }
        for (int ic = 0; ic < 6; ic++) {
            float4 w4[9];
            const u64* wp = (const u64*)w4;
            #pragma unroll
            for (int v = 0; v < 9; v++)
                w4[v] = ((const float4*)(sw3 + och * 216 + ic * 36))[v];
            #pragma unroll
            for (int u = 0; u < 3; u++) {
                const float* bp = sAb + img * 1536 + ic * 256 + (4 * ti_[u]) * 16 + 4 * tj_[u];
                #pragma unroll
                for (int row = 0; row < 8; row++) {
                    float2 rv2[4];
                    const u64* rp = (const u64*)rv2;
                    #pragma unroll
                    for (int h = 0; h < 4; h++)
                        rv2[h] = *(const float2*)(bp + row * 16 + 2 * h);
                    if (row < 6) {
                        #pragma unroll
                        for (int j = 0; j < 3; j++) {
                            fma2(acc[u][0], wp[row * 3 + j], rp[j]);
                            fma2(acc[u][1], wp[row * 3 + j], rp[j + 1]);
                        }
                    }
                    if (row >= 2) {
                        #pragma unroll
                        for (int j = 0; j < 3; j++) {
                            fma2(acc[u][2], wp[(row - 2) * 3 + j], rp[j]);
                            fma2(acc[u][3], wp[(row - 2) * 3 + j], rp[j + 1]);
                        }
                    }
                }
            }
        }
        float* ob = g_B + (img0 + img) * 576 + och * 36;
        #pragma unroll
        for (int u = 0; u < 3; u++) {
            int r0 = 2 * ti_[u], c0 = 2 * tj_[u];
            ob[r0 * 6 + c0]           = ACT_SCALE * fast_tanh(hsum2(acc[u][0]) + bias);
            ob[r0 * 6 + c0 + 1]       = ACT_SCALE * fast_tanh(hsum2(acc[u][1]) + bias);
            ob[(r0 + 1) * 6 + c0]     = ACT_SCALE * fast_tanh(hsum2(acc[u][2]) + bias);
            ob[(r0 + 1) * 6 + c0 + 1] = ACT_SCALE * fast_tanh(hsum2(acc[u][3]) + bias);
        }
    }
}

// ---------------------------------------------------------------------------
// K3: C5 16->120 conv5x5 on 6x6 -> [2,2] positions (+bias).
// 28 images/block, 224 threads, 24-channel weight chunks [400][25] (5 exact
// chunks).  grid = 293 <= 296 concurrent CTAs -> single wave.
// ---------------------------------------------------------------------------
#define K3_IMG 28
#define K3_CHK 24
#define K3_THREADS 224
#define K3_INSTRIDE 584
#define K3_WSTRIDE  25
#define K3_SMEM ((K3_IMG * K3_INSTRIDE + 400 * K3_WSTRIDE) * 4)
#define K3_GRID ((8192 + K3_IMG - 1) / K3_IMG)

__global__ void __launch_bounds__(K3_THREADS) k3(const float* __restrict__ c5_w,
                                                 const float* __restrict__ c5_b) {
    extern __shared__ __align__(16) float sm3[];
    float* sin = sm3;                         // [28][584]
    float* swt = sm3 + K3_IMG * K3_INSTRIDE;  // [400][25] (k-major, ch minor)
    int t = threadIdx.x;
    long imgbase = (long)blockIdx.x * K3_IMG;
    for (int idx = t; idx < K3_IMG * 576; idx += K3_THREADS) {
        int im = idx / 576, off = idx % 576;
        long gi = imgbase + im;
        sin[im * K3_INSTRIDE + off] = (gi < 8192) ? g_B[gi * 576 + off] : 0.f;
    }
    int cg = t & 7;   // channel group (3 channels each, 8 groups = 24 ch)
    int pg = t >> 3;  // local image index 0..27
    const float* ip = sin + pg * K3_INSTRIDE;
    long gimg = imgbase + pg;
    float* outp = g_C + gimg * 480;

    for (int chunk = 0; chunk < 120; chunk += K3_CHK) {
        __syncthreads();
        for (int idx = t; idx < K3_CHK * 400; idx += K3_THREADS) {
            int ch = idx / 400, k = idx % 400;
            swt[k * K3_WSTRIDE + ch] = c5_w[(long)(chunk + ch) * 400 + k];
        }
        __syncthreads();

        float acc[4][3];
        #pragma unroll
        for (int p = 0; p < 4; p++)
            #pragma unroll
            for (int c = 0; c < 3; c++) acc[p][c] = 0.f;

        for (int ic = 0; ic < 16; ic++) {
            float4 pv4[9];
            float* pv = (float*)pv4;
            #pragma unroll
            for (int v = 0; v < 9; v++)
                pv4[v] = ((const float4*)(ip + ic * 36))[v];
            #pragma unroll
            for (int r = 0; r < 5; r++) {
                #pragma unroll
                for (int s = 0; s < 5; s++) {
                    const float* wk = swt + (ic * 25 + r * 5 + s) * K3_WSTRIDE + cg * 3;
                    float w0 = wk[0], w1 = wk[1], w2 = wk[2];
                    #pragma unroll
                    for (int pi = 0; pi < 2; pi++)
                        #pragma unroll
                        for (int pj = 0; pj < 2; pj++) {
                            float v = pv[(pi + r) * 6 + pj + s];
                            int p = pi * 2 + pj;
                            acc[p][0] = fmaf(v, w0, acc[p][0]);
                            acc[p][1] = fmaf(v, w1, acc[p][1]);
                            acc[p][2] = fmaf(v, w2, acc[p][2]);
                        }
                }
            }
        }
        if (gimg < 8192) {
            #pragma unroll
            for (int cc = 0; cc < 3; cc++) {
                int ch = chunk + cg * 3 + cc;
                float b = c5_b[ch];
                float4 o;
                o.x = acc[0][cc] + b;
                o.y = acc[1][cc] + b;
                o.z = acc[2][cc] + b;
                o.w = acc[3][cc] + b;
                *(float4*)(outp + ch * 4) = o;
            }
        }
    }
}

// ---------------------------------------------------------------------------
// K4: F6 (120->84) + act + RBF.  112 rows/block, 448 threads, one wave.
// Weights n-major [84][122]; FFMA2 over k (u64 loads, 72 regs, 2 CTAs).
// ---------------------------------------------------------------------------
#define K4_ROWS 112
#define K4_THREADS 448
#define K4_GRID ((32768 + K4_ROWS - 1) / K4_ROWS)
#define K4_SMEM ((K4_ROWS * 122 + 84 * 122 + 840 + 84) * 4)

__global__ void __launch_bounds__(K4_THREADS) k4(const float* __restrict__ f6_w,
                                                 const float* __restrict__ f6_b,
                                                 const float* __restrict__ rbf_w,
                                                 float* __restrict__ out) {
    extern __shared__ __align__(16) float sm4[];
    float* srow = sm4;                   // [112][122]; later overlaid by sh [112][85]
    float* swt  = srow + K4_ROWS * 122;  // [84][122]  (n-major, pre-scaled)
    float* srbf = swt + 84 * 122;        // [84][10]
    float* sb6  = srbf + 840;            // [84]
    float* sh   = srow;                  // overlay
    int t = threadIdx.x, blk = blockIdx.x;
    long row0 = (long)blk * K4_ROWS;
    int nrows = (int)min((long)K4_ROWS, 32768l - row0);

    for (int idx = t; idx < K4_ROWS * 120; idx += K4_THREADS) {
        int r = idx / 120, k = idx % 120;
        srow[r * 122 + k] = (r < nrows) ? g_C[(row0 + r) * 120 + k] : 0.f;
    }
    for (int idx = t; idx < 84 * 120; idx += K4_THREADS) {
        int n = idx / 120, k = idx % 120;
        swt[n * 122 + k] = ACT_SLOPE * f6_w[idx];
    }
    for (int idx = t; idx < 840; idx += K4_THREADS) srbf[idx] = rbf_w[idx];
    if (t < 84) sb6[t] = ACT_SLOPE * f6_b[t];
    __syncthreads();

    int rg = t >> 4;    // 28 row-groups of 4 rows
    int cl = t & 15;    // column lane
    u64 acc[4][6];
    #pragma unroll
    for (int i = 0; i < 4; i++)
        #pragma unroll
        for (int q = 0; q < 6; q++) acc[i][q] = 0;

    const float* r0 = srow + (rg * 4 + 0) * 122;
    const float* r1 = srow + (rg * 4 + 1) * 122;
    const float* r2 = srow + (rg * 4 + 2) * 122;
    const float* r3 = srow + (rg * 4 + 3) * 122;
    for (int k = 0; k < 120; k += 2) {
        u64 v0 = *(const u64*)(r0 + k);
        u64 v1 = *(const u64*)(r1 + k);
        u64 v2 = *(const u64*)(r2 + k);
        u64 v3 = *(const u64*)(r3 + k);
        #pragma unroll
        for (int q = 0; q < 6; q++) {
            int n = cl + 16 * q;
            if (n < 84) {
                u64 w = *(const u64*)(swt + n * 122 + k);
                fma2(acc[0][q], v0, w);
                fma2(acc[1][q], v1, w);
                fma2(acc[2][q], v2, w);
                fma2(acc[3][q], v3, w);
            }
        }
    }
    float hv[4][6];
    #pragma unroll
    for (int q = 0; q < 6; q++) {
        int n = cl + 16 * q;
        if (n < 84) {
            float bias = sb6[n];
            #pragma unroll
            for (int i = 0; i < 4; i++)
                hv[i][q] = ACT_SCALE * fast_tanh(hsum2(acc[i][q]) + bias);
        }
    }
    __syncthreads();   // all reads of srow done before sh overlay writes
    #pragma unroll
    for (int q = 0; q < 6; q++) {
        int n = cl + 16 * q;
        if (n < 84) {
            #pragma unroll
            for (int i = 0; i < 4; i++)
                sh[(rg * 4 + i) * 85 + n] = hv[i][q];
        }
    }
    __syncthreads();

    for (int idx = t; idx < K4_ROWS * 10; idx += K4_THREADS) {
        int r = idx / 10, o = idx % 10;
        if (r < nrows) {
            const float* hr = sh + r * 85;
            float s = 0.f;
            #pragma unroll 4
            for (int n = 0; n < 84; n++) {
                float d = hr[n] - srbf[n * 10 + o];
                s = fmaf(d, d, s);
            }
            out[(row0 + r) * 10 + o] = s;
        }
    }
}

// ---------------------------------------------------------------------------
extern "C" void kernel_launch(void* const* d_in, const int* in_sizes, int n_in,
                              void* d_out, int out_size) {
    const float* x     = (const float*)d_in[0];
    const float* c1_w  = (const float*)d_in[1];
    const float* c1_b  = (const float*)d_in[2];
    const float* s2_w  = (const float*)d_in[3];
    const float* s2_b  = (const float*)d_in[4];
    const float* c3_w  = (const float*)d_in[5];
    const float* c3_b  = (const float*)d_in[6];
    const float* s4_w  = (const float*)d_in[7];
    const float* s4_b  = (const float*)d_in[8];
    const float* c5_w  = (const float*)d_in[9];
    const float* c5_b  = (const float*)d_in[10];
    const float* f6_w  = (const float*)d_in[11];
    const float* f6_b  = (const float*)d_in[12];
    const float* rbf_w = (const float*)d_in[13];

    cudaFuncSetAttribute(k12, cudaFuncAttributeMaxDynamicSharedMemorySize, K12_SMEM);
    cudaFuncSetAttribute(k3, cudaFuncAttributeMaxDynamicSharedMemorySize, K3_SMEM);
    cudaFuncSetAttribute(k4, cudaFuncAttributeMaxDynamicSharedMemorySize, K4_SMEM);

    k_prep<<<1, 256>>>(c1_w, c1_b, s2_w, s2_b, c3_w, c3_b, s4_w, s4_b);
    k12<<<8192 / K12_IMG, K12_THREADS, K12_SMEM>>>(x);
    k3<<<K3_GRID, K3_THREADS, K3_SMEM>>>(c5_w, c5_b);
    k4<<<K4_GRID, K4_THREADS, K4_SMEM>>>(f6_w, f6_b, rbf_w, (float*)d_out);
}